// round 1
// baseline (speedup 1.0000x reference)
#include <cuda_runtime.h>

// Gent hyperelastic energy, elementwise over N 3x3 deformation gradients.
//   C = F^T F ; I1 = tr(C) = ||F||_F^2 ; J = det(F)
//   I1bar = I1 * J^(-2/3)
//   vol = (J^2 - 1)/2 - log(J)
//   w = -(G/2)*JM * log(1 - (I1bar - 3)/JM) + (K/2)*vol^4
//
// Constants: E=75000, NU=0.3, JM=100 -> G = E/(2(1+NU)) = 28846.153846...
//                                       K = E/(3(1-2NU)) = 62500
// Pre-folded: A = -(G/2)*JM = -1442307.6923..., B = K/2 = 31250.

#define THREADS 256
#define FLOATS_PER_BLOCK (THREADS * 9)        // 2304 floats = 9216 bytes
#define VEC4_PER_BLOCK   (FLOATS_PER_BLOCK/4) // 576

__global__ __launch_bounds__(THREADS)
void gent_kernel(const float* __restrict__ x, float* __restrict__ w, int n)
{
    __shared__ float sx[FLOATS_PER_BLOCK];

    const int tid = threadIdx.x;
    const long long blk_base_f = (long long)blockIdx.x * FLOATS_PER_BLOCK;

    // Coalesced staging: 576 float4 per block, 128B-aligned block chunks.
    const float4* gx4 = reinterpret_cast<const float4*>(x + blk_base_f);
    float4* sx4 = reinterpret_cast<float4*>(sx);
    #pragma unroll
    for (int i = tid; i < VEC4_PER_BLOCK; i += THREADS) {
        sx4[i] = gx4[i];
    }
    __syncthreads();

    // Each thread: one matrix, 9 floats at stride-9 in shared (bank-conflict free).
    const float* m = sx + tid * 9;
    float a00 = m[0], a01 = m[1], a02 = m[2];
    float a10 = m[3], a11 = m[4], a12 = m[5];
    float a20 = m[6], a21 = m[7], a22 = m[8];

    // I1 = Frobenius norm squared
    float I1 = a00*a00 + a01*a01 + a02*a02
             + a10*a10 + a11*a11 + a12*a12
             + a20*a20 + a21*a21 + a22*a22;

    // J = det(F)
    float J = a00*(a11*a22 - a12*a21)
            - a01*(a10*a22 - a12*a20)
            + a02*(a10*a21 - a11*a20);

    // J^(-2/3) via cbrt
    float c = cbrtf(J);
    float Jm23 = 1.0f / (c * c);

    float I1bar = I1 * Jm23;

    float lnJ = logf(J);
    float vol = 0.5f * (J*J - 1.0f) - lnJ;
    float vol2 = vol * vol;
    float vol4 = vol2 * vol2;

    const float JM_ = 100.0f;
    const float A  = -1442307.6923076923f;  // -(G/2)*JM
    const float B  = 31250.0f;              // K/2

    float arg = 1.0f - (I1bar - 3.0f) * (1.0f / JM_);
    float wv = A * logf(arg) + B * vol4;

    int gi = blockIdx.x * THREADS + tid;
    if (gi < n) w[gi] = wv;
}

extern "C" void kernel_launch(void* const* d_in, const int* in_sizes, int n_in,
                              void* d_out, int out_size)
{
    const float* x = (const float*)d_in[0];
    float* w = (float*)d_out;
    const int n = out_size;                 // number of matrices (4,000,000)
    const int blocks = (n + THREADS - 1) / THREADS;  // 15625, exact
    gent_kernel<<<blocks, THREADS>>>(x, w, n);
}

// round 2
// speedup vs baseline: 1.0815x; 1.0815x over previous
#include <cuda_runtime.h>
#include <cstdint>

// Gent hyperelastic energy, elementwise over N 3x3 deformation gradients.
//   I1 = ||F||_F^2 ; J = det(F)
//   I1bar = I1 * J^(-2/3)
//   vol = (J^2 - 1)/2 - log(J)
//   w = -(G/2)*JM * log(1 - (I1bar - 3)/JM) + (K/2)*vol^4
// Constants pre-folded: A = -(G/2)*JM = -1442307.6923..., B = K/2 = 31250.

#define THREADS 256
#define MPT 4                                   // matrices per thread
#define MATS_PER_BLOCK (THREADS * MPT)          // 1024
#define FLOATS_PER_BLOCK (MATS_PER_BLOCK * 9)   // 9216 floats = 36 KB
#define VEC4_PER_BLOCK (FLOATS_PER_BLOCK / 4)   // 2304 -> 9 per thread

__device__ __forceinline__ void cp_async16(void* smem_dst, const void* gmem_src) {
    uint32_t s = (uint32_t)__cvta_generic_to_shared(smem_dst);
    asm volatile("cp.async.cg.shared.global [%0], [%1], 16;\n"
                 :: "r"(s), "l"(gmem_src));
}

__global__ __launch_bounds__(THREADS)
void gent_kernel(const float* __restrict__ x, float* __restrict__ w, int n)
{
    __shared__ float sx[FLOATS_PER_BLOCK];

    const int tid = threadIdx.x;
    const long long base_f4 = (long long)blockIdx.x * VEC4_PER_BLOCK;
    const long long total_f4 = ((long long)n * 9) / 4;   // n*9 = 36M, divisible by 4

    const float4* gx4 = reinterpret_cast<const float4*>(x);
    float4* sx4 = reinterpret_cast<float4*>(sx);

    // 9 independent async 16B copies per thread, fully coalesced per wavefront.
    #pragma unroll
    for (int i = 0; i < 9; i++) {
        int idx = tid + i * THREADS;
        long long g4 = base_f4 + idx;
        if (g4 < total_f4) {
            cp_async16(&sx4[idx], &gx4[g4]);
        }
    }
    asm volatile("cp.async.commit_group;\n");
    asm volatile("cp.async.wait_group 0;\n" ::: "memory");
    __syncthreads();

    const float JM_inv = 0.01f;             // 1/JM
    const float A = -1442307.6923076923f;   // -(G/2)*JM
    const float B = 31250.0f;               // K/2

    const long long mat_base = (long long)blockIdx.x * MATS_PER_BLOCK;

    #pragma unroll
    for (int m = 0; m < MPT; m++) {
        const int local = tid + m * THREADS;        // matrix index within block
        const long long gi = mat_base + local;
        if (gi < n) {
            const float* mm = sx + local * 9;        // stride-9: bank-conflict free
            float a00 = mm[0], a01 = mm[1], a02 = mm[2];
            float a10 = mm[3], a11 = mm[4], a12 = mm[5];
            float a20 = mm[6], a21 = mm[7], a22 = mm[8];

            float I1 = a00*a00 + a01*a01 + a02*a02
                     + a10*a10 + a11*a11 + a12*a12
                     + a20*a20 + a21*a21 + a22*a22;

            float J = a00*(a11*a22 - a12*a21)
                    - a01*(a10*a22 - a12*a20)
                    + a02*(a10*a21 - a11*a20);

            float c = cbrtf(J);
            float Jm23 = 1.0f / (c * c);
            float I1bar = I1 * Jm23;

            float lnJ = logf(J);
            float vol = 0.5f * (J*J - 1.0f) - lnJ;
            float vol2 = vol * vol;
            float vol4 = vol2 * vol2;

            float arg = 1.0f - (I1bar - 3.0f) * JM_inv;
            w[gi] = A * logf(arg) + B * vol4;
        }
    }
}

extern "C" void kernel_launch(void* const* d_in, const int* in_sizes, int n_in,
                              void* d_out, int out_size)
{
    const float* x = (const float*)d_in[0];
    float* w = (float*)d_out;
    const int n = out_size;  // 4,000,000 matrices
    const int blocks = (n + MATS_PER_BLOCK - 1) / MATS_PER_BLOCK;  // 3907
    gent_kernel<<<blocks, THREADS>>>(x, w, n);
}